// round 15
// baseline (speedup 1.0000x reference)
#include <cuda_runtime.h>
#include <cuda_fp16.h>
#include <math.h>

#define NB 8192
#define NSLICE 37              // 4 x-blocks * 37 slices = 148 blocks = 1 block/SM
#define PSTRIDE 38             // padded partial stride; pad slot stays 0
#define RPT 4                  // rows per thread in attention
#define RSTRIDE (NB / RPT)     // 2048
#define NPAIR (RPT / 2)        // 2 packed row-pairs
#define JMAX 222               // max j per slice
#define NPREPB 128             // prep blocks (64 rows each, 4x redundant threads)
#define LOG2E 1.4426950408889634f

typedef unsigned int u32;

// ---- scratch (device globals; no allocation allowed) ----
__device__ float4 gQ4[NB];                 // q * (0.5*log2e) per row (fp32)
__device__ float  gQn[NB];                 // |q_tilde| per row
__device__ uint4  gKh[NB];                 // {h2(kx,kx), h2(ky,ky), h2(kz,kz), h2(kw,kw)}
__device__ u32    gCh[NB];                 // h2(c,c), c = x . conv_w
__device__ __align__(16) float gKmaxBlk[NPREPB];  // per-prep-block max |k|
__device__ float4 gP[NB * PSTRIDE / 2];    // {sum,y} float2 pairs, padded

__device__ __forceinline__ __half2 u2h(u32 v) { __half2 h; *reinterpret_cast<u32*>(&h) = v; return h; }
__device__ __forceinline__ u32 h2u(__half2 h) { return *reinterpret_cast<u32*>(&h); }
__device__ __forceinline__ __half2 hexp2_x(__half2 v) {
    u32 r, s = h2u(v);
    asm("ex2.approx.f16x2 %0, %1;" : "=r"(r) : "r"(s));
    return u2h(r);
}
__device__ __forceinline__ float tanh_hw(float x) {
    float y;
    asm("tanh.approx.f32 %0, %1;" : "=f"(y) : "f"(x));
    return y;
}

// ---- smem weight layout (float offsets); vector rows 16B-aligned ----
#define O_WFM   0
#define O_BFM   128
#define O_WC1   144
#define O_BC1   400
#define O_WP1   416
#define O_BP1   608
#define O_WC2   620
#define O_BC2   716
#define O_WP2   724
#define O_BP2   756
#define O_WC3   760
#define O_BC3   776
#define O_ROT   780
#define O_ENT   796
#define O_CW    812
#define SM_FLOATS 816

// full-row layer: one thread computes ALL NO outputs (NO independent FMA chains,
// no cross-lane exchange). Weight reads are warp-uniform -> LDS broadcasts.
template<int NI, int NO>
__device__ __forceinline__ void layer1(const float* __restrict__ smw, int woff, int boff,
                                       const float* __restrict__ xin,
                                       float* __restrict__ xout)
{
    float acc[NO];
    #pragma unroll
    for (int o = 0; o < NO; o++) acc[o] = smw[boff + o];
    #pragma unroll
    for (int i = 0; i < NI; i++) {
        float xi = xin[i];
        #pragma unroll
        for (int g = 0; g < NO / 4; g++) {
            float4 w = *reinterpret_cast<const float4*>(smw + woff + i * NO + 4 * g);
            acc[4*g+0] = fmaf(xi, w.x, acc[4*g+0]);
            acc[4*g+1] = fmaf(xi, w.y, acc[4*g+1]);
            acc[4*g+2] = fmaf(xi, w.z, acc[4*g+2]);
            acc[4*g+3] = fmaf(xi, w.w, acc[4*g+3]);
        }
    }
    #pragma unroll
    for (int o = 0; o < NO; o++) xout[o] = tanh_hw(acc[o]);
}

__device__ __forceinline__ void stage(float* dst, const float* src, int n, int tid, int nthr) {
    for (int i = tid; i < n; i += nthr) dst[i] = src[i];
}

// ---------- Kernel A: MLP chain, full row/thread, 4x redundancy for occupancy ----------
// 256 threads = 64 rows * 4 redundant copies; lanes (tid&3)!=0 duplicate compute
// (free: fma pipe ~5% busy) and write nothing. Zero shuffles.
__global__ void __launch_bounds__(256) k_prep(
                       const float* __restrict__ inp,
                       const float* __restrict__ Wfm, const float* __restrict__ bfm,
                       const float* __restrict__ Wc1, const float* __restrict__ bc1,
                       const float* __restrict__ Wp1, const float* __restrict__ bp1,
                       const float* __restrict__ Wc2, const float* __restrict__ bc2,
                       const float* __restrict__ Wp2, const float* __restrict__ bp2,
                       const float* __restrict__ Wc3, const float* __restrict__ bc3,
                       const float* __restrict__ rot, const float* __restrict__ ent,
                       const float* __restrict__ conv_w)
{
    __shared__ __align__(16) float sm[SM_FLOATS];
    __shared__ float smKn[64];
    int tid = threadIdx.x;
    stage(sm + O_WFM, Wfm, 128, tid, 256);
    stage(sm + O_BFM, bfm, 16,  tid, 256);
    stage(sm + O_WC1, Wc1, 256, tid, 256);
    stage(sm + O_BC1, bc1, 16,  tid, 256);
    stage(sm + O_WP1, Wp1, 192, tid, 256);
    stage(sm + O_BP1, bp1, 12,  tid, 256);
    stage(sm + O_WC2, Wc2, 96,  tid, 256);
    stage(sm + O_BC2, bc2, 8,   tid, 256);
    stage(sm + O_WP2, Wp2, 32,  tid, 256);
    stage(sm + O_BP2, bp2, 4,   tid, 256);
    stage(sm + O_WC3, Wc3, 16,  tid, 256);
    stage(sm + O_BC3, bc3, 4,   tid, 256);
    stage(sm + O_ROT, rot, 16,  tid, 256);
    stage(sm + O_ENT, ent, 16,  tid, 256);
    stage(sm + O_CW,  conv_w, 4, tid, 256);
    __syncthreads();

    int r = blockIdx.x * 64 + (tid >> 2);   // row (4 redundant threads each)

    float x0[16], x1[16];
    {
        const float4* ip = reinterpret_cast<const float4*>(inp + r * 8);
        float4 v0 = __ldg(ip), v1 = __ldg(ip + 1);
        x0[0]=v0.x; x0[1]=v0.y; x0[2]=v0.z; x0[3]=v0.w;
        x0[4]=v1.x; x0[5]=v1.y; x0[6]=v1.z; x0[7]=v1.w;
    }

    layer1<8, 16>(sm, O_WFM, O_BFM, x0, x1);
    layer1<16,16>(sm, O_WC1, O_BC1, x1, x0);
    layer1<16,12>(sm, O_WP1, O_BP1, x0, x1);
    layer1<12, 8>(sm, O_WC2, O_BC2, x1, x0);
    layer1<8,  4>(sm, O_WP2, O_BP2, x0, x1);
    layer1<4,  4>(sm, O_WC3, O_BC3, x1, x0);   // final x in x0[0..3]

    if ((tid & 3) == 0) {
        float qv[4], kv[4];
        #pragma unroll
        for (int c = 0; c < 4; c++) {
            float sq = 0.f, sk = 0.f;
            #pragma unroll
            for (int i = 0; i < 4; i++) {
                sq = fmaf(x0[i], sm[O_ROT + i * 4 + c], sq);
                sk = fmaf(x0[i], sm[O_ENT + i * 4 + c], sk);
            }
            qv[c] = sq * (0.5f * LOG2E);
            kv[c] = sk;
        }

        gQ4[r] = make_float4(qv[0], qv[1], qv[2], qv[3]);
        float qn = sqrtf(qv[0]*qv[0] + qv[1]*qv[1] + qv[2]*qv[2] + qv[3]*qv[3]);
        gQn[r] = qn;
        float kn = sqrtf(kv[0]*kv[0] + kv[1]*kv[1] + kv[2]*kv[2] + kv[3]*kv[3]);
        smKn[tid >> 2] = kn;

        uint4 kk;
        kk.x = h2u(__floats2half2_rn(kv[0], kv[0]));
        kk.y = h2u(__floats2half2_rn(kv[1], kv[1]));
        kk.z = h2u(__floats2half2_rn(kv[2], kv[2]));
        kk.w = h2u(__floats2half2_rn(kv[3], kv[3]));
        gKh[r] = kk;
        float cc = fmaf(x0[0], sm[O_CW+0], fmaf(x0[1], sm[O_CW+1],
                   fmaf(x0[2], sm[O_CW+2], x0[3] * sm[O_CW+3])));
        gCh[r] = h2u(__floats2half2_rn(cc, cc));
    }
    __syncthreads();
    if (tid == 0) {
        float m = smKn[0];
        #pragma unroll
        for (int i = 1; i < 64; i++) m = fmaxf(m, smKn[i]);
        gKmaxBlk[blockIdx.x] = m;
    }
}

// ---------- Kernel B: streaming attention, full-fp16 inner loop (R10-proven) ----------
__global__ void __launch_bounds__(512) k_attn() {
    __shared__ uint4 smK[JMAX];
    __shared__ u32   smC[JMAX];

    int tid   = threadIdx.x;
    int t     = blockIdx.x * 512 + tid;   // 0..RSTRIDE-1
    int slice = blockIdx.y;

    int j0  = (slice * NB) / NSLICE;
    int cnt = ((slice + 1) * NB) / NSLICE - j0;

    if (tid < cnt) {
        smK[tid] = gKh[j0 + tid];
        smC[tid] = gCh[j0 + tid];
    }

    float kmax = 0.f;
    {
        const float4* km4 = reinterpret_cast<const float4*>(gKmaxBlk);
        #pragma unroll
        for (int i = 0; i < NPREPB / 4; i++) {
            float4 v = __ldg(km4 + i);
            kmax = fmaxf(kmax, fmaxf(fmaxf(v.x, v.y), fmaxf(v.z, v.w)));
        }
    }

    __half2 qx[NPAIR], qy[NPAIR], qz[NPAIR], qw[NPAIR], nmh[NPAIR];
    float sA[NPAIR], sB[NPAIR], yA[NPAIR], yB[NPAIR];

    #pragma unroll
    for (int p = 0; p < NPAIR; p++) {
        int r0 = t + (2 * p)     * RSTRIDE;
        int r1 = t + (2 * p + 1) * RSTRIDE;
        float4 qa = gQ4[r0];
        float4 qb = gQ4[r1];
        qx[p] = __floats2half2_rn(qa.x, qb.x);
        qy[p] = __floats2half2_rn(qa.y, qb.y);
        qz[p] = __floats2half2_rn(qa.z, qb.z);
        qw[p] = __floats2half2_rn(qa.w, qb.w);
        nmh[p] = __floats2half2_rn(-gQn[r0] * kmax, -gQn[r1] * kmax);
        sA[p] = 0.f; sB[p] = 0.f; yA[p] = 0.f; yB[p] = 0.f;
    }

    __syncthreads();

    const __half2 hz = __float2half2_rn(0.f);
    int nfull = cnt >> 3;

    for (int c8 = 0; c8 < nfull; c8++) {
        __half2 sh[NPAIR], yh[NPAIR];
        #pragma unroll
        for (int p = 0; p < NPAIR; p++) { sh[p] = hz; yh[p] = hz; }
        int base = c8 * 8;
        #pragma unroll
        for (int u = 0; u < 8; u++) {
            uint4 kk = smK[base + u];
            __half2 kx = u2h(kk.x), ky = u2h(kk.y), kz = u2h(kk.z), kw = u2h(kk.w);
            __half2 ch = u2h(smC[base + u]);
            #pragma unroll
            for (int p = 0; p < NPAIR; p++) {
                __half2 s = __hfma2(qx[p], kx, nmh[p]);
                s = __hfma2(qy[p], ky, s);
                s = __hfma2(qz[p], kz, s);
                s = __hfma2(qw[p], kw, s);
                __half2 e = hexp2_x(s);
                sh[p] = __hadd2(sh[p], e);
                yh[p] = __hfma2(e, ch, yh[p]);
            }
        }
        #pragma unroll
        for (int p = 0; p < NPAIR; p++) {
            sA[p] += __low2float(sh[p]);  sB[p] += __high2float(sh[p]);
            yA[p] += __low2float(yh[p]);  yB[p] += __high2float(yh[p]);
        }
    }
    {
        __half2 sh[NPAIR], yh[NPAIR];
        #pragma unroll
        for (int p = 0; p < NPAIR; p++) { sh[p] = hz; yh[p] = hz; }
        for (int j = nfull * 8; j < cnt; j++) {
            uint4 kk = smK[j];
            __half2 kx = u2h(kk.x), ky = u2h(kk.y), kz = u2h(kk.z), kw = u2h(kk.w);
            __half2 ch = u2h(smC[j]);
            #pragma unroll
            for (int p = 0; p < NPAIR; p++) {
                __half2 s = __hfma2(qx[p], kx, nmh[p]);
                s = __hfma2(qy[p], ky, s);
                s = __hfma2(qz[p], kz, s);
                s = __hfma2(qw[p], kw, s);
                __half2 e = hexp2_x(s);
                sh[p] = __hadd2(sh[p], e);
                yh[p] = __hfma2(e, ch, yh[p]);
            }
        }
        #pragma unroll
        for (int p = 0; p < NPAIR; p++) {
            sA[p] += __low2float(sh[p]);  sB[p] += __high2float(sh[p]);
            yA[p] += __low2float(yh[p]);  yB[p] += __high2float(yh[p]);
        }
    }

    float2* __restrict__ gp2 = reinterpret_cast<float2*>(gP);
    #pragma unroll
    for (int p = 0; p < NPAIR; p++) {
        int r0 = t + (2 * p)     * RSTRIDE;
        int r1 = t + (2 * p + 1) * RSTRIDE;
        gp2[r0 * PSTRIDE + slice] = make_float2(sA[p], yA[p]);
        gp2[r1 * PSTRIDE + slice] = make_float2(sB[p], yB[p]);
    }
}

// ---------- Kernel C: reduce slices (4 lanes/row) + conv-sigmoid + head-sigmoid ----------
__global__ void __launch_bounds__(256) k_tail(
                       const float* __restrict__ conv_b,
                       const float* __restrict__ head_w, const float* __restrict__ head_b,
                       float* __restrict__ out)
{
    int tid = blockIdx.x * 256 + threadIdx.x;
    int row = tid >> 2;          // 4 lanes per row
    int l   = tid & 3;

    const float4* __restrict__ p = gP + row * (PSTRIDE / 2);
    float sum = 0.f, y = 0.f;
    #pragma unroll
    for (int i = l; i < PSTRIDE / 2; i += 4) {
        float4 v = __ldg(p + i);      // {sum0, y0, sum1, y1}
        sum += v.x + v.z;
        y   += v.y + v.w;
    }
    sum += __shfl_xor_sync(0xffffffffu, sum, 1, 4);
    y   += __shfl_xor_sync(0xffffffffu, y,   1, 4);
    sum += __shfl_xor_sync(0xffffffffu, sum, 2, 4);
    y   += __shfl_xor_sync(0xffffffffu, y,   2, 4);

    if (l == 0) {
        float z = fmaf(y, 1.f / sum, conv_b[0]);
        float f = 1.f / (1.f + expf(-z));
        float logit = fmaf(f, head_w[0], head_b[0]);
        out[row] = 1.f / (1.f + expf(-logit));
    }
}

extern "C" void kernel_launch(void* const* d_in, const int* in_sizes, int n_in,
                              void* d_out, int out_size)
{
    const float* inp  = (const float*)d_in[0];
    const float* Wfm  = (const float*)d_in[1];
    const float* bfm  = (const float*)d_in[2];
    const float* Wc1  = (const float*)d_in[3];
    const float* bc1  = (const float*)d_in[4];
    const float* Wp1  = (const float*)d_in[5];
    const float* bp1  = (const float*)d_in[6];
    const float* Wc2  = (const float*)d_in[7];
    const float* bc2  = (const float*)d_in[8];
    const float* Wp2  = (const float*)d_in[9];
    const float* bp2  = (const float*)d_in[10];
    const float* Wc3  = (const float*)d_in[11];
    const float* bc3  = (const float*)d_in[12];
    const float* rot  = (const float*)d_in[13];
    const float* ent  = (const float*)d_in[14];
    const float* cw   = (const float*)d_in[15];
    const float* cb   = (const float*)d_in[16];
    const float* hw   = (const float*)d_in[17];
    const float* hb   = (const float*)d_in[18];
    float* out = (float*)d_out;

    k_prep<<<NPREPB, 256>>>(inp, Wfm, bfm, Wc1, bc1, Wp1, bp1,
                            Wc2, bc2, Wp2, bp2, Wc3, bc3, rot, ent, cw);
    dim3 gridB(RSTRIDE / 512, NSLICE);   // 4 x 37 = 148 blocks, 16 warps each
    k_attn<<<gridB, 512>>>();
    k_tail<<<NB * 4 / 256, 256>>>(cb, hw, hb, out);
}

// round 16
// speedup vs baseline: 1.0094x; 1.0094x over previous
#include <cuda_runtime.h>
#include <cuda_fp16.h>
#include <math.h>

#define NB 8192
#define NSLICE 37              // 4 x-blocks * 37 slices = 148 blocks = 1 block/SM
#define PSTRIDE 38             // padded partial stride; pad slot stays 0
#define JPAD 224               // padded j per slice (28 tiles of 8)
#define NPREPB 128             // prep blocks (64 rows each)
#define LOG2E 1.4426950408889634f

typedef unsigned int u32;

// ---- scratch (device globals; no allocation allowed) ----
__device__ uint2  gQh2[NB];                // {h2(q0,q1), h2(q2,q3)} (q pre-scaled by 0.5*log2e)
__device__ float  gQn[NB];                 // |q_tilde| per row
__device__ uint2  gKh2[NB];                // {h2(k0,k1), h2(k2,k3)}
__device__ __half gChalf[NB];              // c = x . conv_w (fp16)
__device__ __align__(16) float gKmaxBlk[NPREPB];  // per-prep-block max |k|
__device__ float4 gP[NB * PSTRIDE / 2];    // {sum,y} float2 pairs, padded

__device__ __forceinline__ __half2 u2h(u32 v) { __half2 h; *reinterpret_cast<u32*>(&h) = v; return h; }
__device__ __forceinline__ u32 h2u(__half2 h) { return *reinterpret_cast<u32*>(&h); }
__device__ __forceinline__ u32 hexp2_u(u32 s) {
    u32 r;
    asm("ex2.approx.f16x2 %0, %1;" : "=r"(r) : "r"(s));
    return r;
}
__device__ __forceinline__ float tanh_hw(float x) {
    float y;
    asm("tanh.approx.f32 %0, %1;" : "=f"(y) : "f"(x));
    return y;
}
// m16n8k16 f16 mma, A/B/C/D fragments per PTX ISA; a2=a3=b1=0 (k dims 4..15 are zero)
__device__ __forceinline__ void mma16816(u32& d0, u32& d1, u32 a0, u32 a1,
                                         u32 b0, u32 c0, u32 c1) {
    asm("mma.sync.aligned.m16n8k16.row.col.f16.f16.f16.f16 "
        "{%0,%1}, {%2,%3,%4,%5}, {%6,%7}, {%8,%9};"
        : "=r"(d0), "=r"(d1)
        : "r"(a0), "r"(a1), "r"(0u), "r"(0u), "r"(b0), "r"(0u), "r"(c0), "r"(c1));
}

// ---- smem weight layout (float offsets) ----
#define O_WFM   0
#define O_BFM   128
#define O_WC1   144
#define O_BC1   400
#define O_WP1   416
#define O_BP1   608
#define O_WC2   620
#define O_BC2   716
#define O_WP2   724
#define O_BP2   756
#define O_WC3   760
#define O_BC3   776
#define O_ROT   780
#define O_ENT   796
#define O_CW    812
#define SM_FLOATS 816

template<int NI, int NO>
__device__ __forceinline__ void layer4(const float* __restrict__ smw, int woff, int boff,
                                       int q, const float* __restrict__ xin,
                                       float* __restrict__ xout_full)
{
    constexpr int NOq = NO / 4;
    float acc[NOq];
    #pragma unroll
    for (int oo = 0; oo < NOq; oo++) acc[oo] = smw[boff + q * NOq + oo];
    #pragma unroll
    for (int i = 0; i < NI; i++) {
        float xi = xin[i];
        if constexpr (NOq == 4) {
            float4 w = *reinterpret_cast<const float4*>(smw + woff + i * NO + q * 4);
            acc[0] = fmaf(xi, w.x, acc[0]);
            acc[1] = fmaf(xi, w.y, acc[1]);
            acc[2] = fmaf(xi, w.z, acc[2]);
            acc[3] = fmaf(xi, w.w, acc[3]);
        } else if constexpr (NOq == 2) {
            float2 w = *reinterpret_cast<const float2*>(smw + woff + i * NO + q * 2);
            acc[0] = fmaf(xi, w.x, acc[0]);
            acc[1] = fmaf(xi, w.y, acc[1]);
        } else {
            #pragma unroll
            for (int oo = 0; oo < NOq; oo++)
                acc[oo] = fmaf(xi, smw[woff + i * NO + q * NOq + oo], acc[oo]);
        }
    }
    float loc[NOq];
    #pragma unroll
    for (int oo = 0; oo < NOq; oo++) loc[oo] = tanh_hw(acc[oo]);
    #pragma unroll
    for (int i = 0; i < NO; i++)
        xout_full[i] = __shfl_sync(0xffffffffu, loc[i % NOq], i / NOq, 4);
}

__device__ __forceinline__ void stage(float* dst, const float* src, int n, int tid, int nthr) {
    for (int i = tid; i < n; i += nthr) dst[i] = src[i];
}

// ---------- Kernel A: MLP chain, 4 lanes per row (R10-proven structure) ----------
__global__ void __launch_bounds__(256) k_prep(
                       const float* __restrict__ inp,
                       const float* __restrict__ Wfm, const float* __restrict__ bfm,
                       const float* __restrict__ Wc1, const float* __restrict__ bc1,
                       const float* __restrict__ Wp1, const float* __restrict__ bp1,
                       const float* __restrict__ Wc2, const float* __restrict__ bc2,
                       const float* __restrict__ Wp2, const float* __restrict__ bp2,
                       const float* __restrict__ Wc3, const float* __restrict__ bc3,
                       const float* __restrict__ rot, const float* __restrict__ ent,
                       const float* __restrict__ conv_w)
{
    __shared__ __align__(16) float sm[SM_FLOATS];
    __shared__ float smKn[64];
    int tid = threadIdx.x;
    stage(sm + O_WFM, Wfm, 128, tid, 256);
    stage(sm + O_BFM, bfm, 16,  tid, 256);
    stage(sm + O_WC1, Wc1, 256, tid, 256);
    stage(sm + O_BC1, bc1, 16,  tid, 256);
    stage(sm + O_WP1, Wp1, 192, tid, 256);
    stage(sm + O_BP1, bp1, 12,  tid, 256);
    stage(sm + O_WC2, Wc2, 96,  tid, 256);
    stage(sm + O_BC2, bc2, 8,   tid, 256);
    stage(sm + O_WP2, Wp2, 32,  tid, 256);
    stage(sm + O_BP2, bp2, 4,   tid, 256);
    stage(sm + O_WC3, Wc3, 16,  tid, 256);
    stage(sm + O_BC3, bc3, 4,   tid, 256);
    stage(sm + O_ROT, rot, 16,  tid, 256);
    stage(sm + O_ENT, ent, 16,  tid, 256);
    stage(sm + O_CW,  conv_w, 4, tid, 256);
    __syncthreads();

    int r = blockIdx.x * 64 + (tid >> 2);   // row
    int q = tid & 3;                        // lane within row

    float x0[16], x1[16];
    {
        const float4* ip = reinterpret_cast<const float4*>(inp + r * 8);
        float4 v0 = __ldg(ip), v1 = __ldg(ip + 1);
        x0[0]=v0.x; x0[1]=v0.y; x0[2]=v0.z; x0[3]=v0.w;
        x0[4]=v1.x; x0[5]=v1.y; x0[6]=v1.z; x0[7]=v1.w;
    }

    layer4<8, 16>(sm, O_WFM, O_BFM, q, x0, x1);
    layer4<16,16>(sm, O_WC1, O_BC1, q, x1, x0);
    layer4<16,12>(sm, O_WP1, O_BP1, q, x0, x1);
    layer4<12, 8>(sm, O_WC2, O_BC2, q, x1, x0);
    layer4<8,  4>(sm, O_WP2, O_BP2, q, x0, x1);
    layer4<4,  4>(sm, O_WC3, O_BC3, q, x1, x0);   // final x in x0[0..3]

    if (q == 0) {
        float qv[4], kv[4];
        #pragma unroll
        for (int c = 0; c < 4; c++) {
            float sq = 0.f, sk = 0.f;
            #pragma unroll
            for (int i = 0; i < 4; i++) {
                sq = fmaf(x0[i], sm[O_ROT + i * 4 + c], sq);
                sk = fmaf(x0[i], sm[O_ENT + i * 4 + c], sk);
            }
            qv[c] = sq * (0.5f * LOG2E);
            kv[c] = sk;
        }

        uint2 qq;
        qq.x = h2u(__floats2half2_rn(qv[0], qv[1]));
        qq.y = h2u(__floats2half2_rn(qv[2], qv[3]));
        gQh2[r] = qq;
        float qn = sqrtf(qv[0]*qv[0] + qv[1]*qv[1] + qv[2]*qv[2] + qv[3]*qv[3]);
        gQn[r] = qn;
        float kn = sqrtf(kv[0]*kv[0] + kv[1]*kv[1] + kv[2]*kv[2] + kv[3]*kv[3]);
        smKn[tid >> 2] = kn;

        uint2 kk;
        kk.x = h2u(__floats2half2_rn(kv[0], kv[1]));
        kk.y = h2u(__floats2half2_rn(kv[2], kv[3]));
        gKh2[r] = kk;
        float cc = fmaf(x0[0], sm[O_CW+0], fmaf(x0[1], sm[O_CW+1],
                   fmaf(x0[2], sm[O_CW+2], x0[3] * sm[O_CW+3])));
        gChalf[r] = __float2half(cc);
    }
    __syncthreads();
    if (tid == 0) {
        float m = smKn[0];
        #pragma unroll
        for (int i = 1; i < 64; i++) m = fmaxf(m, smKn[i]);
        gKmaxBlk[blockIdx.x] = m;
    }
}

// ---------- Kernel B: HMMA attention (m16n8k16), exp2 on D fragments ----------
__global__ void __launch_bounds__(512) k_attn() {
    __shared__ uint2  smK2[JPAD];     // {h2(k0,k1), h2(k2,k3)} per j
    __shared__ __half smC[JPAD];      // c per j

    int tid   = threadIdx.x;
    int slice = blockIdx.y;
    int xg    = blockIdx.x;

    int j0  = (slice * NB) / NSLICE;
    int cnt = ((slice + 1) * NB) / NSLICE - j0;     // 221 or 222
    int rem = cnt - 216;                            // valid cols in tile 27 (5 or 6)

    if (tid < JPAD) {
        if (tid < cnt) {
            smK2[tid] = gKh2[j0 + tid];
            smC[tid]  = gChalf[j0 + tid];
        } else {
            smK2[tid] = make_uint2(0u, 0u);
            smC[tid]  = __float2half(0.f);
        }
    }

    float kmax = 0.f;
    {
        const float4* km4 = reinterpret_cast<const float4*>(gKmaxBlk);
        #pragma unroll
        for (int i = 0; i < NPREPB / 4; i++) {
            float4 v = __ldg(km4 + i);
            kmax = fmaxf(kmax, fmaxf(fmaxf(v.x, v.y), fmaxf(v.z, v.w)));
        }
    }

    __syncthreads();

    int w    = tid >> 5;          // warp 0..15
    int lane = tid & 31;
    int g    = lane >> 2;         // groupID (row within tile / j within tile)
    int tg   = lane & 3;          // thread-in-group

    const u32* __restrict__ kp  = reinterpret_cast<const u32*>(smK2);  // 448 u32
    const u32* __restrict__ cpp = reinterpret_cast<const u32*>(smC);   // 112 u32

    // last-tile column mask (cols 2tg, 2tg+1 of tile 27)
    u32 maskh = h2u(__floats2half2_rn((2*tg   < rem) ? 1.f : 0.f,
                                      (2*tg+1 < rem) ? 1.f : 0.f));

    float2* __restrict__ gp2 = reinterpret_cast<float2*>(gP);
    const __half2 hz = __float2half2_rn(0.f);

    #pragma unroll 1
    for (int rt = 0; rt < 8; rt++) {
        int L0 = (w * 8 + rt) * 16;                       // local row-tile base (0..2032)
        int row_base = xg * 512 + (L0 >> 9) * 2048 + (L0 & 511);
        int row_g  = row_base + g;
        int row_g8 = row_g + 8;

        // A fragments: rows g, g+8; k = 2tg,2tg+1 (zero for tg>=2 and k>=4)
        uint2 uqg  = __ldg(reinterpret_cast<const uint2*>(gQh2) + row_g);
        uint2 uqg8 = __ldg(reinterpret_cast<const uint2*>(gQh2) + row_g8);
        u32 a0 = (tg == 0) ? uqg.x  : (tg == 1) ? uqg.y  : 0u;
        u32 a1 = (tg == 0) ? uqg8.x : (tg == 1) ? uqg8.y : 0u;

        // C fragments: -m per row, broadcast across cols
        u32 c0 = h2u(__float2half2_rn(-__ldg(gQn + row_g)  * kmax));
        u32 c1 = h2u(__float2half2_rn(-__ldg(gQn + row_g8) * kmax));

        float S0 = 0.f, S1 = 0.f, Y0 = 0.f, Y1 = 0.f;
        __half2 sA = hz, sB = hz, yA = hz, yB = hz;

        #pragma unroll 4
        for (int jt = 0; jt < 28; jt++) {
            // B fragment: k = 2tg,2tg+1 ; j (col) = jt*8 + g
            u32 b0 = (tg < 2) ? kp[(jt * 8 + g) * 2 + tg] : 0u;
            u32 cpu = cpp[jt * 4 + tg];    // c at cols (jt*8+2tg, +1)

            u32 d0, d1;
            mma16816(d0, d1, a0, a1, b0, c0, c1);

            u32 e0u = hexp2_u(d0);
            u32 e1u = hexp2_u(d1);
            if (jt == 27) { e0u = h2u(__hmul2(u2h(e0u), u2h(maskh)));
                            e1u = h2u(__hmul2(u2h(e1u), u2h(maskh))); }

            __half2 e0 = u2h(e0u), e1 = u2h(e1u), cp = u2h(cpu);
            sA = __hadd2(sA, e0);
            sB = __hadd2(sB, e1);
            yA = __hfma2(e0, cp, yA);
            yB = __hfma2(e1, cp, yB);

            if ((jt & 3) == 3) {            // flush every 4 tiles (32 j)
                S0 += __low2float(sA) + __high2float(sA);
                S1 += __low2float(sB) + __high2float(sB);
                Y0 += __low2float(yA) + __high2float(yA);
                Y1 += __low2float(yB) + __high2float(yB);
                sA = hz; sB = hz; yA = hz; yB = hz;
            }
        }

        // reduce over the 4 threads of each row group (cols split across tg)
        S0 += __shfl_xor_sync(0xffffffffu, S0, 1, 4);
        S1 += __shfl_xor_sync(0xffffffffu, S1, 1, 4);
        Y0 += __shfl_xor_sync(0xffffffffu, Y0, 1, 4);
        Y1 += __shfl_xor_sync(0xffffffffu, Y1, 1, 4);
        S0 += __shfl_xor_sync(0xffffffffu, S0, 2, 4);
        S1 += __shfl_xor_sync(0xffffffffu, S1, 2, 4);
        Y0 += __shfl_xor_sync(0xffffffffu, Y0, 2, 4);
        Y1 += __shfl_xor_sync(0xffffffffu, Y1, 2, 4);

        if (tg == 0) {
            gp2[row_g  * PSTRIDE + slice] = make_float2(S0, Y0);
            gp2[row_g8 * PSTRIDE + slice] = make_float2(S1, Y1);
        }
    }
}

// ---------- Kernel C: reduce slices (4 lanes/row) + conv-sigmoid + head-sigmoid ----------
__global__ void __launch_bounds__(256) k_tail(
                       const float* __restrict__ conv_b,
                       const float* __restrict__ head_w, const float* __restrict__ head_b,
                       float* __restrict__ out)
{
    int tid = blockIdx.x * 256 + threadIdx.x;
    int row = tid >> 2;          // 4 lanes per row
    int l   = tid & 3;

    const float4* __restrict__ p = gP + row * (PSTRIDE / 2);
    float sum = 0.f, y = 0.f;
    #pragma unroll
    for (int i = l; i < PSTRIDE / 2; i += 4) {
        float4 v = __ldg(p + i);      // {sum0, y0, sum1, y1}
        sum += v.x + v.z;
        y   += v.y + v.w;
    }
    sum += __shfl_xor_sync(0xffffffffu, sum, 1, 4);
    y   += __shfl_xor_sync(0xffffffffu, y,   1, 4);
    sum += __shfl_xor_sync(0xffffffffu, sum, 2, 4);
    y   += __shfl_xor_sync(0xffffffffu, y,   2, 4);

    if (l == 0) {
        float z = fmaf(y, 1.f / sum, conv_b[0]);
        float f = 1.f / (1.f + expf(-z));
        float logit = fmaf(f, head_w[0], head_b[0]);
        out[row] = 1.f / (1.f + expf(-logit));
    }
}

extern "C" void kernel_launch(void* const* d_in, const int* in_sizes, int n_in,
                              void* d_out, int out_size)
{
    const float* inp  = (const float*)d_in[0];
    const float* Wfm  = (const float*)d_in[1];
    const float* bfm  = (const float*)d_in[2];
    const float* Wc1  = (const float*)d_in[3];
    const float* bc1  = (const float*)d_in[4];
    const float* Wp1  = (const float*)d_in[5];
    const float* bp1  = (const float*)d_in[6];
    const float* Wc2  = (const float*)d_in[7];
    const float* bc2  = (const float*)d_in[8];
    const float* Wp2  = (const float*)d_in[9];
    const float* bp2  = (const float*)d_in[10];
    const float* Wc3  = (const float*)d_in[11];
    const float* bc3  = (const float*)d_in[12];
    const float* rot  = (const float*)d_in[13];
    const float* ent  = (const float*)d_in[14];
    const float* cw   = (const float*)d_in[15];
    const float* cb   = (const float*)d_in[16];
    const float* hw   = (const float*)d_in[17];
    const float* hb   = (const float*)d_in[18];
    float* out = (float*)d_out;

    k_prep<<<NPREPB, 256>>>(inp, Wfm, bfm, Wc1, bc1, Wp1, bp1,
                            Wc2, bc2, Wp2, bp2, Wc3, bc3, rot, ent, cw);
    dim3 gridB(4, NSLICE);               // 4 x 37 = 148 blocks, 16 warps each
    k_attn<<<gridB, 512>>>();
    k_tail<<<NB * 4 / 256, 256>>>(cb, hw, hb, out);
}

// round 17
// speedup vs baseline: 1.0452x; 1.0355x over previous
#include <cuda_runtime.h>
#include <cuda_fp16.h>
#include <math.h>

#define NB 8192
#define NSLICE 37              // 4 x-blocks * 37 slices = 148 blocks = 1 block/SM
#define RPT 4                  // rows per thread in attention
#define RSTRIDE (NB / RPT)     // 2048
#define NPAIR (RPT / 2)        // 2 packed row-pairs
#define JMAX 222               // max j per slice
#define NPREPB 128             // prep blocks (64 rows each)
#define LOG2E 1.4426950408889634f

typedef unsigned int u32;

// ---- scratch (device globals; no allocation allowed) ----
__device__ float4 gQ4[NB];                 // q * (0.5*log2e) per row (fp32)
__device__ float  gQn[NB];                 // |q_tilde| per row
__device__ uint4  gKh[NB];                 // {h2(kx,kx), h2(ky,ky), h2(kz,kz), h2(kw,kw)}
__device__ u32    gCh[NB];                 // h2(c,c), c = x . conv_w
__device__ __align__(16) float gKmaxBlk[NPREPB];  // per-prep-block max |k|
__device__ float2 gPs[NSLICE * NB];        // {sum,y} SLICE-MAJOR: [slice][row] (coalesced)

__device__ __forceinline__ __half2 u2h(u32 v) { __half2 h; *reinterpret_cast<u32*>(&h) = v; return h; }
__device__ __forceinline__ u32 h2u(__half2 h) { return *reinterpret_cast<u32*>(&h); }
__device__ __forceinline__ __half2 hexp2_x(__half2 v) {
    u32 r, s = h2u(v);
    asm("ex2.approx.f16x2 %0, %1;" : "=r"(r) : "r"(s));
    return u2h(r);
}
__device__ __forceinline__ float tanh_hw(float x) {
    float y;
    asm("tanh.approx.f32 %0, %1;" : "=f"(y) : "f"(x));
    return y;
}

// ---- smem weight layout (float offsets) ----
#define O_WFM   0
#define O_BFM   128
#define O_WC1   144
#define O_BC1   400
#define O_WP1   416
#define O_BP1   608
#define O_WC2   620
#define O_BC2   716
#define O_WP2   724
#define O_BP2   756
#define O_WC3   760
#define O_BC3   776
#define O_ROT   780
#define O_ENT   796
#define O_CW    812
#define SM_FLOATS 816

template<int NI, int NO>
__device__ __forceinline__ void layer4(const float* __restrict__ smw, int woff, int boff,
                                       int q, const float* __restrict__ xin,
                                       float* __restrict__ xout_full)
{
    constexpr int NOq = NO / 4;
    float acc[NOq];
    #pragma unroll
    for (int oo = 0; oo < NOq; oo++) acc[oo] = smw[boff + q * NOq + oo];
    #pragma unroll
    for (int i = 0; i < NI; i++) {
        float xi = xin[i];
        if constexpr (NOq == 4) {
            float4 w = *reinterpret_cast<const float4*>(smw + woff + i * NO + q * 4);
            acc[0] = fmaf(xi, w.x, acc[0]);
            acc[1] = fmaf(xi, w.y, acc[1]);
            acc[2] = fmaf(xi, w.z, acc[2]);
            acc[3] = fmaf(xi, w.w, acc[3]);
        } else if constexpr (NOq == 2) {
            float2 w = *reinterpret_cast<const float2*>(smw + woff + i * NO + q * 2);
            acc[0] = fmaf(xi, w.x, acc[0]);
            acc[1] = fmaf(xi, w.y, acc[1]);
        } else {
            #pragma unroll
            for (int oo = 0; oo < NOq; oo++)
                acc[oo] = fmaf(xi, smw[woff + i * NO + q * NOq + oo], acc[oo]);
        }
    }
    float loc[NOq];
    #pragma unroll
    for (int oo = 0; oo < NOq; oo++) loc[oo] = tanh_hw(acc[oo]);
    #pragma unroll
    for (int i = 0; i < NO; i++)
        xout_full[i] = __shfl_sync(0xffffffffu, loc[i % NOq], i / NOq, 4);
}

__device__ __forceinline__ void stage(float* dst, const float* src, int n, int tid, int nthr) {
    for (int i = tid; i < n; i += nthr) dst[i] = src[i];
}

// ---------- Kernel A: MLP chain, 4 lanes per row (R10-proven, unchanged) ----------
__global__ void __launch_bounds__(256) k_prep(
                       const float* __restrict__ inp,
                       const float* __restrict__ Wfm, const float* __restrict__ bfm,
                       const float* __restrict__ Wc1, const float* __restrict__ bc1,
                       const float* __restrict__ Wp1, const float* __restrict__ bp1,
                       const float* __restrict__ Wc2, const float* __restrict__ bc2,
                       const float* __restrict__ Wp2, const float* __restrict__ bp2,
                       const float* __restrict__ Wc3, const float* __restrict__ bc3,
                       const float* __restrict__ rot, const float* __restrict__ ent,
                       const float* __restrict__ conv_w)
{
    __shared__ __align__(16) float sm[SM_FLOATS];
    __shared__ float smKn[64];
    int tid = threadIdx.x;
    stage(sm + O_WFM, Wfm, 128, tid, 256);
    stage(sm + O_BFM, bfm, 16,  tid, 256);
    stage(sm + O_WC1, Wc1, 256, tid, 256);
    stage(sm + O_BC1, bc1, 16,  tid, 256);
    stage(sm + O_WP1, Wp1, 192, tid, 256);
    stage(sm + O_BP1, bp1, 12,  tid, 256);
    stage(sm + O_WC2, Wc2, 96,  tid, 256);
    stage(sm + O_BC2, bc2, 8,   tid, 256);
    stage(sm + O_WP2, Wp2, 32,  tid, 256);
    stage(sm + O_BP2, bp2, 4,   tid, 256);
    stage(sm + O_WC3, Wc3, 16,  tid, 256);
    stage(sm + O_BC3, bc3, 4,   tid, 256);
    stage(sm + O_ROT, rot, 16,  tid, 256);
    stage(sm + O_ENT, ent, 16,  tid, 256);
    stage(sm + O_CW,  conv_w, 4, tid, 256);
    __syncthreads();

    int r = blockIdx.x * 64 + (tid >> 2);   // row
    int q = tid & 3;                        // lane within row

    float x0[16], x1[16];
    {
        const float4* ip = reinterpret_cast<const float4*>(inp + r * 8);
        float4 v0 = __ldg(ip), v1 = __ldg(ip + 1);
        x0[0]=v0.x; x0[1]=v0.y; x0[2]=v0.z; x0[3]=v0.w;
        x0[4]=v1.x; x0[5]=v1.y; x0[6]=v1.z; x0[7]=v1.w;
    }

    layer4<8, 16>(sm, O_WFM, O_BFM, q, x0, x1);
    layer4<16,16>(sm, O_WC1, O_BC1, q, x1, x0);
    layer4<16,12>(sm, O_WP1, O_BP1, q, x0, x1);
    layer4<12, 8>(sm, O_WC2, O_BC2, q, x1, x0);
    layer4<8,  4>(sm, O_WP2, O_BP2, q, x0, x1);
    layer4<4,  4>(sm, O_WC3, O_BC3, q, x1, x0);   // final x in x0[0..3]

    if (q == 0) {
        float qv[4], kv[4];
        #pragma unroll
        for (int c = 0; c < 4; c++) {
            float sq = 0.f, sk = 0.f;
            #pragma unroll
            for (int i = 0; i < 4; i++) {
                sq = fmaf(x0[i], sm[O_ROT + i * 4 + c], sq);
                sk = fmaf(x0[i], sm[O_ENT + i * 4 + c], sk);
            }
            qv[c] = sq * (0.5f * LOG2E);
            kv[c] = sk;
        }

        gQ4[r] = make_float4(qv[0], qv[1], qv[2], qv[3]);
        float qn = sqrtf(qv[0]*qv[0] + qv[1]*qv[1] + qv[2]*qv[2] + qv[3]*qv[3]);
        gQn[r] = qn;
        float kn = sqrtf(kv[0]*kv[0] + kv[1]*kv[1] + kv[2]*kv[2] + kv[3]*kv[3]);
        smKn[tid >> 2] = kn;

        uint4 kk;
        kk.x = h2u(__floats2half2_rn(kv[0], kv[0]));
        kk.y = h2u(__floats2half2_rn(kv[1], kv[1]));
        kk.z = h2u(__floats2half2_rn(kv[2], kv[2]));
        kk.w = h2u(__floats2half2_rn(kv[3], kv[3]));
        gKh[r] = kk;
        float cc = fmaf(x0[0], sm[O_CW+0], fmaf(x0[1], sm[O_CW+1],
                   fmaf(x0[2], sm[O_CW+2], x0[3] * sm[O_CW+3])));
        gCh[r] = h2u(__floats2half2_rn(cc, cc));
    }
    __syncthreads();
    if (tid == 0) {
        float m = smKn[0];
        #pragma unroll
        for (int i = 1; i < 64; i++) m = fmaxf(m, smKn[i]);
        gKmaxBlk[blockIdx.x] = m;
    }
}

// ---------- Kernel B: streaming attention, fp16 loop (R10) + coalesced stores ----------
__global__ void __launch_bounds__(512) k_attn() {
    __shared__ uint4 smK[JMAX];
    __shared__ u32   smC[JMAX];

    int tid   = threadIdx.x;
    int t     = blockIdx.x * 512 + tid;   // 0..RSTRIDE-1
    int slice = blockIdx.y;

    int j0  = (slice * NB) / NSLICE;
    int cnt = ((slice + 1) * NB) / NSLICE - j0;

    if (tid < cnt) {
        smK[tid] = gKh[j0 + tid];
        smC[tid] = gCh[j0 + tid];
    }

    float kmax = 0.f;
    {
        const float4* km4 = reinterpret_cast<const float4*>(gKmaxBlk);
        #pragma unroll
        for (int i = 0; i < NPREPB / 4; i++) {
            float4 v = __ldg(km4 + i);
            kmax = fmaxf(kmax, fmaxf(fmaxf(v.x, v.y), fmaxf(v.z, v.w)));
        }
    }

    __half2 qx[NPAIR], qy[NPAIR], qz[NPAIR], qw[NPAIR], nmh[NPAIR];
    float sA[NPAIR], sB[NPAIR], yA[NPAIR], yB[NPAIR];

    #pragma unroll
    for (int p = 0; p < NPAIR; p++) {
        int r0 = t + (2 * p)     * RSTRIDE;
        int r1 = t + (2 * p + 1) * RSTRIDE;
        float4 qa = gQ4[r0];
        float4 qb = gQ4[r1];
        qx[p] = __floats2half2_rn(qa.x, qb.x);
        qy[p] = __floats2half2_rn(qa.y, qb.y);
        qz[p] = __floats2half2_rn(qa.z, qb.z);
        qw[p] = __floats2half2_rn(qa.w, qb.w);
        nmh[p] = __floats2half2_rn(-gQn[r0] * kmax, -gQn[r1] * kmax);
        sA[p] = 0.f; sB[p] = 0.f; yA[p] = 0.f; yB[p] = 0.f;
    }

    __syncthreads();

    const __half2 hz = __float2half2_rn(0.f);
    int nfull = cnt >> 3;

    for (int c8 = 0; c8 < nfull; c8++) {
        __half2 sh[NPAIR], yh[NPAIR];
        #pragma unroll
        for (int p = 0; p < NPAIR; p++) { sh[p] = hz; yh[p] = hz; }
        int base = c8 * 8;
        #pragma unroll
        for (int u = 0; u < 8; u++) {
            uint4 kk = smK[base + u];
            __half2 kx = u2h(kk.x), ky = u2h(kk.y), kz = u2h(kk.z), kw = u2h(kk.w);
            __half2 ch = u2h(smC[base + u]);
            #pragma unroll
            for (int p = 0; p < NPAIR; p++) {
                __half2 s = __hfma2(qx[p], kx, nmh[p]);
                s = __hfma2(qy[p], ky, s);
                s = __hfma2(qz[p], kz, s);
                s = __hfma2(qw[p], kw, s);
                __half2 e = hexp2_x(s);
                sh[p] = __hadd2(sh[p], e);
                yh[p] = __hfma2(e, ch, yh[p]);
            }
        }
        #pragma unroll
        for (int p = 0; p < NPAIR; p++) {
            sA[p] += __low2float(sh[p]);  sB[p] += __high2float(sh[p]);
            yA[p] += __low2float(yh[p]);  yB[p] += __high2float(yh[p]);
        }
    }
    {
        __half2 sh[NPAIR], yh[NPAIR];
        #pragma unroll
        for (int p = 0; p < NPAIR; p++) { sh[p] = hz; yh[p] = hz; }
        for (int j = nfull * 8; j < cnt; j++) {
            uint4 kk = smK[j];
            __half2 kx = u2h(kk.x), ky = u2h(kk.y), kz = u2h(kk.z), kw = u2h(kk.w);
            __half2 ch = u2h(smC[j]);
            #pragma unroll
            for (int p = 0; p < NPAIR; p++) {
                __half2 s = __hfma2(qx[p], kx, nmh[p]);
                s = __hfma2(qy[p], ky, s);
                s = __hfma2(qz[p], kz, s);
                s = __hfma2(qw[p], kw, s);
                __half2 e = hexp2_x(s);
                sh[p] = __hadd2(sh[p], e);
                yh[p] = __hfma2(e, ch, yh[p]);
            }
        }
        #pragma unroll
        for (int p = 0; p < NPAIR; p++) {
            sA[p] += __low2float(sh[p]);  sB[p] += __high2float(sh[p]);
            yA[p] += __low2float(yh[p]);  yB[p] += __high2float(yh[p]);
        }
    }

    // slice-major partials: consecutive tid -> consecutive rows -> coalesced 256B/warp
    float2* __restrict__ base = gPs + slice * NB;
    #pragma unroll
    for (int p = 0; p < NPAIR; p++) {
        int r0 = t + (2 * p)     * RSTRIDE;
        int r1 = t + (2 * p + 1) * RSTRIDE;
        base[r0] = make_float2(sA[p], yA[p]);
        base[r1] = make_float2(sB[p], yB[p]);
    }
}

// ---------- Kernel C: thread/row reduce (coalesced stride-NB loads) + sigmoids ----------
__global__ void __launch_bounds__(256) k_tail(
                       const float* __restrict__ conv_b,
                       const float* __restrict__ head_w, const float* __restrict__ head_b,
                       float* __restrict__ out)
{
    int row = blockIdx.x * 256 + threadIdx.x;

    float sum = 0.f, y = 0.f;
    #pragma unroll
    for (int s = 0; s < NSLICE; s++) {
        float2 v = __ldg(gPs + s * NB + row);   // warp: 32 consecutive rows -> coalesced
        sum += v.x;
        y   += v.y;
    }
    float z = fmaf(y, 1.f / sum, conv_b[0]);
    float f = 1.f / (1.f + expf(-z));
    float logit = fmaf(f, head_w[0], head_b[0]);
    out[row] = 1.f / (1.f + expf(-logit));
}

extern "C" void kernel_launch(void* const* d_in, const int* in_sizes, int n_in,
                              void* d_out, int out_size)
{
    const float* inp  = (const float*)d_in[0];
    const float* Wfm  = (const float*)d_in[1];
    const float* bfm  = (const float*)d_in[2];
    const float* Wc1  = (const float*)d_in[3];
    const float* bc1  = (const float*)d_in[4];
    const float* Wp1  = (const float*)d_in[5];
    const float* bp1  = (const float*)d_in[6];
    const float* Wc2  = (const float*)d_in[7];
    const float* bc2  = (const float*)d_in[8];
    const float* Wp2  = (const float*)d_in[9];
    const float* bp2  = (const float*)d_in[10];
    const float* Wc3  = (const float*)d_in[11];
    const float* bc3  = (const float*)d_in[12];
    const float* rot  = (const float*)d_in[13];
    const float* ent  = (const float*)d_in[14];
    const float* cw   = (const float*)d_in[15];
    const float* cb   = (const float*)d_in[16];
    const float* hw   = (const float*)d_in[17];
    const float* hb   = (const float*)d_in[18];
    float* out = (float*)d_out;

    k_prep<<<NPREPB, 256>>>(inp, Wfm, bfm, Wc1, bc1, Wp1, bp1,
                            Wc2, bc2, Wp2, bp2, Wc3, bc3, rot, ent, cw);
    dim3 gridB(RSTRIDE / 512, NSLICE);   // 4 x 37 = 148 blocks, 16 warps each
    k_attn<<<gridB, 512>>>();
    k_tail<<<NB / 256, 256>>>(cb, hw, hb, out);
}